// round 8
// baseline (speedup 1.0000x reference)
#include <cuda_runtime.h>
#include <cuda_fp16.h>
#include <math.h>
#include <stdint.h>

#define B_    512
#define E_    1024
#define ML_   50
#define V_    50000
#define G4E_  (4*E_)
#define KGATE 2048           // gates K: [words|ctx] vs [w_ih|w_hh]

// ---------------- scratch (__device__ globals; allocation-free rule) --------
__device__ float g_af32[B_*KGATE];              // [words | ctx] fp32
__device__ float g_gates[(long long)B_*G4E_];
__device__ int   g_pad_byte_mode;

// ---------------- PTX helpers (arch-stable, sm_80-era) ----------------------
__device__ __forceinline__ uint32_t smem_u32(const void* p) {
    uint32_t a;
    asm("{ .reg .u64 t; cvta.to.shared.u64 t, %1; cvt.u32.u64 %0, t; }" : "=r"(a) : "l"(p));
    return a;
}
__device__ __forceinline__ void ldsm_x4(uint32_t addr, uint32_t& r0, uint32_t& r1,
                                        uint32_t& r2, uint32_t& r3) {
    asm volatile("ldmatrix.sync.aligned.m8n8.x4.shared.b16 {%0,%1,%2,%3}, [%4];"
                 : "=r"(r0), "=r"(r1), "=r"(r2), "=r"(r3) : "r"(addr));
}
__device__ __forceinline__ void mma16816(float* c, const uint32_t* a, const uint32_t* b) {
    asm volatile("mma.sync.aligned.m16n8k16.row.col.f32.f16.f16.f32 "
                 "{%0,%1,%2,%3}, {%4,%5,%6,%7}, {%8,%9}, {%0,%1,%2,%3};"
                 : "+f"(c[0]), "+f"(c[1]), "+f"(c[2]), "+f"(c[3])
                 : "r"(a[0]), "r"(a[1]), "r"(a[2]), "r"(a[3]), "r"(b[0]), "r"(b[1]));
}
#define STS64(addr, u0, u1) \
    asm volatile("st.shared.v2.b32 [%0], {%1,%2};" :: "r"(addr), "r"(u0), "r"(u1) : "memory")
__device__ __forceinline__ uint32_t swz128(uint32_t o) { return o ^ ((o >> 3) & 0x70); }

__device__ __forceinline__ uint32_t pack_hi(float x, float y) {
    __half2 h = __floats2half2_rn(x, y);
    return *reinterpret_cast<uint32_t*>(&h);
}
__device__ __forceinline__ uint32_t pack_lo(float x, float y, uint32_t hiu) {
    __half2 h = *reinterpret_cast<__half2*>(&hiu);
    float lx = x - __half2float(__low2half(h));
    float ly = y - __half2float(__high2half(h));
    __half2 l = __floats2half2_rn(lx, ly);
    return *reinterpret_cast<uint32_t*>(&l);
}

// ---------------------------------------------------------------------------
// pad dtype detect (robust: bool-as-byte vs int32/float32 0/1)
// ---------------------------------------------------------------------------
__global__ void detect_pad_kernel(const unsigned char* __restrict__ pad) {
    __shared__ int s_gt1, s_off4;
    if (threadIdx.x == 0) { s_gt1 = 0; s_off4 = 0; }
    __syncthreads();
    for (int i = threadIdx.x; i < B_*ML_; i += blockDim.x) {
        unsigned char v = pad[i];
        if (v > 1) atomicOr(&s_gt1, 1);
        if (v != 0 && (i & 3) != 0) atomicOr(&s_off4, 1);
    }
    __syncthreads();
    if (threadIdx.x == 0)
        g_pad_byte_mode = (s_gt1 == 0 && s_off4 != 0) ? 1 : 0;
}

// ---------------------------------------------------------------------------
// Embedding gather -> fp32 A cols [0,1024) of gates GEMM
// ---------------------------------------------------------------------------
__global__ void gather_words_kernel(const int* __restrict__ tgt,
                                    const float* __restrict__ emb) {
    int idx = blockIdx.x * blockDim.x + threadIdx.x;
    if (idx >= B_*E_) return;
    int b = idx >> 10, e = idx & (E_ - 1);
    g_af32[b * KGATE + e] = emb[(long long)tgt[b] * E_ + e];
}

// ---------------------------------------------------------------------------
// Attention -> fp32 ctx into A cols [1024,2048)
// ---------------------------------------------------------------------------
__global__ void attn_kernel(const float* __restrict__ enc,
                            const float* __restrict__ h0,
                            const void* __restrict__ pad_raw) {
    int b = blockIdx.x;
    __shared__ float sh_h[E_];
    __shared__ float sh_w[ML_];
    int tid = threadIdx.x;
    for (int i = tid; i < E_; i += 256) sh_h[i] = h0[(long long)b*E_ + i];
    __syncthreads();
    int w = tid >> 5, lane = tid & 31;
    for (int l = w; l < ML_; l += 8) {
        const float* row = enc + ((long long)b*ML_ + l) * E_;
        float s = 0.f;
        for (int e = lane; e < E_; e += 32) s += row[e] * sh_h[e];
        #pragma unroll
        for (int o = 16; o > 0; o >>= 1) s += __shfl_down_sync(0xffffffffu, s, o);
        if (lane == 0) sh_w[l] = s;
    }
    __syncthreads();
    if (tid == 0) {
        int bm = g_pad_byte_mode;
        const unsigned char* p8 = (const unsigned char*)pad_raw;
        const unsigned int*  pw = (const unsigned int*)pad_raw;
        float mx = -1e30f;
        for (int l = 0; l < ML_; l++) mx = fmaxf(mx, sh_w[l]);
        float sum = 0.f;
        for (int l = 0; l < ML_; l++) {
            bool masked = bm ? (p8[b*ML_ + l] != 0) : (pw[b*ML_ + l] != 0u);
            float v = masked ? 0.f : __expf(sh_w[l] - mx);
            sh_w[l] = v; sum += v;
        }
        float inv = 1.f / sum;
        for (int l = 0; l < ML_; l++) sh_w[l] *= inv;
    }
    __syncthreads();
    for (int e = tid; e < E_; e += 256) {
        const float* base = enc + (long long)b*ML_*E_ + e;
        float acc = 0.f;
        #pragma unroll 10
        for (int l = 0; l < ML_; l++) acc += sh_w[l] * base[(long long)l*E_];
        g_af32[b * KGATE + E_ + e] = acc;
    }
}

// ---------------------------------------------------------------------------
// Fused fp32-in GEMM via fp16x2 mma.sync:
//   C[M,N] = A[M,K] * B[N,K]^T (+bias), inputs fp32, accurate to ~2e-4.
// Per 32-fp32 K-chunk: LDG fp32 -> regs -> split hi/lo fp16 -> swizzled smem:
//   A tile rows: [hi(k0..31) | hi(k0..31)]  (dup)    -> BM x 128B
//   B tile rows: [hi(k0..31) | lo(k0..31)]           -> 128 x 128B
// mma consumes logical K2=64/chunk (A wraps to hi half): hi*hi + hi*lo.
// 3-stage pipeline; B may be split into two segments (B0|B1) along K.
// BM=128: warps 4m x 2n (32x64). BM=64: 2m x 4n (32x32).
// ---------------------------------------------------------------------------
template<int BM>
__global__ void __launch_bounds__(256, (BM == 64) ? 2 : 1) gemm_fused(
    const float* __restrict__ A, int astride,
    const float* __restrict__ B0, const float* __restrict__ B1,
    int ksplit, int bstride, int nbrows,
    float* __restrict__ C, const float* __restrict__ bias,
    int K, int Nreal)
{
    constexpr int WMW = (BM == 128) ? 4 : 2;
    constexpr int WNW = 8 / WMW;
    constexpr int WN  = 128 / WNW;
    constexpr int NT  = WN / 8;
    constexpr int ATILE = BM * 128;          // bytes
    constexpr int STAGE = ATILE + 16384;
    constexpr int APT = BM / 32;             // A float4 per thread
    constexpr int LDT = APT + 4;

    extern __shared__ char smem_raw[];
    const uint32_t smem = smem_u32(smem_raw);

    const int tid = threadIdx.x;
    const int wid = tid >> 5, lane = tid & 31;
    const int wm = wid % WMW, wn = wid / WMW;
    const int m0 = blockIdx.x * BM, n0 = blockIdx.y * 128;
    const int nch = K >> 5;                  // 32 fp32 per chunk

    float4 ld[LDT];

    auto ldg_chunk = [&](int chunk) {
        int kc = chunk * 32;
        #pragma unroll
        for (int j = 0; j < APT; j++) {
            int op = tid + j * 256;
            int row = op >> 3, c4 = op & 7;
            ld[j] = *(const float4*)(A + (long long)(m0 + row) * astride + kc + c4 * 4);
        }
        const float* bp; int kb;
        if (kc < ksplit) { bp = B0; kb = kc; } else { bp = B1; kb = kc - ksplit; }
        #pragma unroll
        for (int j = 0; j < 4; j++) {
            int op = tid + j * 256;
            int row = op >> 3, c4 = op & 7;
            int gn = n0 + row;
            ld[APT + j] = (gn < nbrows)
                ? *(const float4*)(bp + (long long)gn * bstride + kb + c4 * 4)
                : make_float4(0.f, 0.f, 0.f, 0.f);
        }
    };

    auto sts_chunk = [&](int stage) {
        uint32_t sbase = smem + stage * STAGE;
        #pragma unroll
        for (int j = 0; j < APT; j++) {
            int op = tid + j * 256;
            int row = op >> 3, c4 = op & 7;
            float4 v = ld[j];
            uint32_t u0 = pack_hi(v.x, v.y), u1 = pack_hi(v.z, v.w);
            uint32_t o = (uint32_t)(row * 128 + c4 * 8);
            STS64(sbase + swz128(o), u0, u1);
            STS64(sbase + swz128(o + 64), u0, u1);   // duplicate hi
        }
        #pragma unroll
        for (int j = 0; j < 4; j++) {
            int op = tid + j * 256;
            int row = op >> 3, c4 = op & 7;
            float4 v = ld[APT + j];
            uint32_t h0 = pack_hi(v.x, v.y), h1 = pack_hi(v.z, v.w);
            uint32_t l0 = pack_lo(v.x, v.y, h0), l1 = pack_lo(v.z, v.w, h1);
            uint32_t o = (uint32_t)(row * 128 + c4 * 8);
            STS64(sbase + ATILE + swz128(o), h0, h1);
            STS64(sbase + ATILE + swz128(o + 64), l0, l1);
        }
    };

    float acc[2][NT][4];
    #pragma unroll
    for (int mt = 0; mt < 2; mt++)
        #pragma unroll
        for (int nt = 0; nt < NT; nt++)
            #pragma unroll
            for (int q = 0; q < 4; q++) acc[mt][nt][q] = 0.f;

    ldg_chunk(0); sts_chunk(0);
    if (nch > 1) { ldg_chunk(1); sts_chunk(1); }
    __syncthreads();

    const int a_row_in = lane & 15;
    const int a_chunk  = lane >> 4;
    const int b_row_in = (lane & 7) + ((lane & 16) ? 8 : 0);
    const int b_chunk  = (lane >> 3) & 1;

    for (int i = 0; i < nch; i++) {
        if (i + 2 < nch) ldg_chunk(i + 2);

        uint32_t sbase = smem + (i % 3) * STAGE;
        uint32_t As = sbase, Bs = sbase + ATILE;

        #pragma unroll
        for (int ks = 0; ks < 4; ks++) {
            uint32_t a[2][4];
            #pragma unroll
            for (int mt = 0; mt < 2; mt++) {
                int row = wm * 32 + mt * 16 + a_row_in;
                int ch  = ks * 2 + a_chunk;
                uint32_t addr = As + swz128((uint32_t)(row * 128 + ch * 16));
                ldsm_x4(addr, a[mt][0], a[mt][1], a[mt][2], a[mt][3]);
            }
            uint32_t b[NT][2];
            #pragma unroll
            for (int np = 0; np < NT/2; np++) {
                int row = wn * WN + np * 16 + b_row_in;
                int ch  = ks * 2 + b_chunk;
                uint32_t addr = Bs + swz128((uint32_t)(row * 128 + ch * 16));
                ldsm_x4(addr, b[np*2][0], b[np*2][1], b[np*2+1][0], b[np*2+1][1]);
            }
            #pragma unroll
            for (int mt = 0; mt < 2; mt++)
                #pragma unroll
                for (int nt = 0; nt < NT; nt++)
                    mma16816(acc[mt][nt], a[mt], b[nt]);
        }

        if (i + 2 < nch) sts_chunk((i + 2) % 3);
        __syncthreads();
    }

    #pragma unroll
    for (int mt = 0; mt < 2; mt++) {
        int r0g = m0 + wm * 32 + mt * 16 + (lane >> 2);
        #pragma unroll
        for (int nt = 0; nt < NT; nt++) {
            int col = n0 + wn * WN + nt * 8 + (lane & 3) * 2;
            if (col >= Nreal) continue;
            float bx = 0.f, by = 0.f;
            if (bias) { bx = bias[col]; by = bias[col + 1]; }
            float2 v0 = make_float2(acc[mt][nt][0] + bx, acc[mt][nt][1] + by);
            float2 v1 = make_float2(acc[mt][nt][2] + bx, acc[mt][nt][3] + by);
            *(float2*)(C + (long long)r0g * Nreal + col) = v0;
            *(float2*)(C + (long long)(r0g + 8) * Nreal + col) = v1;
        }
    }
}

// ---------------------------------------------------------------------------
// LSTM elementwise (ctx read from g_af32 cols [1024,2048))
// ---------------------------------------------------------------------------
__global__ void lstm_kernel(const float* __restrict__ b_ih,
                            const float* __restrict__ b_hh,
                            float* __restrict__ h_out,
                            float* __restrict__ c_out) {
    int idx = blockIdx.x * blockDim.x + threadIdx.x;
    if (idx >= B_*E_) return;
    int b = idx >> 10, e = idx & (E_ - 1);
    const float* g = g_gates + (long long)b * G4E_;
    float xi = g[e]        + b_ih[e]        + b_hh[e];
    float xf = g[E_   + e] + b_ih[E_   + e] + b_hh[E_   + e];
    float xg = g[2*E_ + e] + b_ih[2*E_ + e] + b_hh[2*E_ + e];
    float xo = g[3*E_ + e] + b_ih[3*E_ + e] + b_hh[3*E_ + e];
    float ig = 1.f / (1.f + __expf(-xi));
    float fg = 1.f / (1.f + __expf(-xf));
    float gg = tanhf(xg);
    float og = 1.f / (1.f + __expf(-xo));
    float c  = fg * g_af32[b * KGATE + E_ + e] + ig * gg;
    float h  = og * tanhf(c);
    h_out[idx] = h;
    c_out[idx] = c;
}

// ---------------------------------------------------------------------------
extern "C" void kernel_launch(void* const* d_in, const int* in_sizes, int n_in,
                              void* d_out, int out_size) {
    const void *p_tgt=0, *p_enc=0, *p_h0=0, *p_pad=0, *p_emb=0, *p_wproj=0,
               *p_wih=0, *p_whh=0, *p_bih=0, *p_bhh=0, *p_bproj=0;
    int seen_be = 0, seen_ve = 0, seen_w = 0, seen_b4 = 0;
    for (int i = 0; i < n_in; i++) {
        long long s = in_sizes[i];
        if      (s == 512)                  p_tgt = d_in[i];
        else if (s == (long long)B_*ML_*E_) p_enc = d_in[i];
        else if (s == (long long)B_*E_)     { if (seen_be++ == 0) p_h0 = d_in[i]; }
        else if (s == B_*ML_)               p_pad = d_in[i];
        else if (s == (long long)V_*E_)     { if (seen_ve++ == 0) p_emb = d_in[i]; else p_wproj = d_in[i]; }
        else if (s == (long long)G4E_*E_)   { if (seen_w++  == 0) p_wih = d_in[i]; else p_whh = d_in[i]; }
        else if (s == G4E_)                 { if (seen_b4++ == 0) p_bih = d_in[i]; else p_bhh = d_in[i]; }
        else if (s == V_)                   p_bproj = d_in[i];
    }

    const int*   tgt    = (const int*)p_tgt;
    const float* enc    = (const float*)p_enc;
    const float* h0     = (const float*)p_h0;
    const float* emb    = (const float*)p_emb;
    const float* w_ih   = (const float*)p_wih;
    const float* w_hh   = (const float*)p_whh;
    const float* b_ih   = (const float*)p_bih;
    const float* b_hh   = (const float*)p_bhh;
    const float* w_proj = (const float*)p_wproj;
    const float* b_proj = (const float*)p_bproj;

    float* out    = (float*)d_out;
    float* logits = out;
    float* h_out  = out + (long long)B_ * V_;
    float* c_out  = h_out + (long long)B_ * E_;

    float *af32, *gates;
    cudaGetSymbolAddress((void**)&af32,  g_af32);
    cudaGetSymbolAddress((void**)&gates, g_gates);

    const int SMEM128 = 3 * (128*128 + 16384);   // 96 KB
    const int SMEM64  = 3 * (64*128 + 16384);    // 72 KB
    cudaFuncSetAttribute(gemm_fused<128>, cudaFuncAttributeMaxDynamicSharedMemorySize, SMEM128);
    cudaFuncSetAttribute(gemm_fused<64>,  cudaFuncAttributeMaxDynamicSharedMemorySize, SMEM64);

    detect_pad_kernel<<<1, 1024>>>((const unsigned char*)p_pad);
    gather_words_kernel<<<(B_*E_ + 255)/256, 256>>>(tgt, emb);
    attn_kernel<<<B_, 256>>>(enc, h0, p_pad);

    // gates GEMM: A=g_af32 [512,2048]; B=[w_ih|w_hh] segmented along K
    {
        dim3 grid(B_/64, G4E_/128);
        gemm_fused<64><<<grid, 256, SMEM64>>>(
            af32, KGATE, w_ih, w_hh, E_, E_, G4E_,
            gates, nullptr, KGATE, G4E_);
    }

    lstm_kernel<<<(B_*E_ + 255)/256, 256>>>(b_ih, b_hh, h_out, c_out);

    // logits GEMM: A=h_out [512,1024]; B=w_proj [50000,1024] (rows >V_ zeroed)
    {
        dim3 grid(B_/128, (V_ + 127)/128);
        gemm_fused<128><<<grid, 256, SMEM128>>>(
            h_out, E_, w_proj, w_proj, E_, E_, V_,
            logits, b_proj, E_, V_);
    }
}

// round 9
// speedup vs baseline: 1.3917x; 1.3917x over previous
#include <cuda_runtime.h>
#include <cuda_fp16.h>
#include <math.h>
#include <stdint.h>

#define B_    512
#define E_    1024
#define ML_   50
#define V_    50000
#define G4E_  (4*E_)
#define NPADV 50048          // V padded to multiple of 128
#define KGATE 2048           // gates K: [words|ctx] vs [w_ih|w_hh]

// ---------------- scratch (__device__ globals; allocation-free rule) --------
__device__ float g_ctx[B_*E_];
__device__ float g_gates[(long long)B_*G4E_];
__device__ int   g_pad_byte_mode;

__device__ __half g_wp[(long long)NPADV*E_];     // w_proj fp16 (rows >= V_ zero)
__device__ __half g_wg[(long long)G4E_*KGATE];   // [w_ih | w_hh] fp16
__device__ __half g_ag[B_*KGATE];                // [words | ctx] fp16
__device__ __half g_h[B_*E_];                    // h_new fp16

union H8 { __half h[8]; uint4 u; };

// ---------------- PTX helpers (arch-stable, sm_80-era) ----------------------
__device__ __forceinline__ uint32_t smem_u32(const void* p) {
    uint32_t a;
    asm("{ .reg .u64 t; cvta.to.shared.u64 t, %1; cvt.u32.u64 %0, t; }" : "=r"(a) : "l"(p));
    return a;
}
#define CP_ASYNC16(dst, src) \
    asm volatile("cp.async.cg.shared.global [%0], [%1], 16;" :: "r"(dst), "l"(src) : "memory")
#define CP_COMMIT() asm volatile("cp.async.commit_group;" ::: "memory")
#define CP_WAIT1()  asm volatile("cp.async.wait_group 1;" ::: "memory")
#define CP_WAIT0()  asm volatile("cp.async.wait_group 0;" ::: "memory")

__device__ __forceinline__ void ldsm_x4(uint32_t addr, uint32_t& r0, uint32_t& r1,
                                        uint32_t& r2, uint32_t& r3) {
    asm volatile("ldmatrix.sync.aligned.m8n8.x4.shared.b16 {%0,%1,%2,%3}, [%4];"
                 : "=r"(r0), "=r"(r1), "=r"(r2), "=r"(r3) : "r"(addr));
}
__device__ __forceinline__ void mma16816(float* c, const uint32_t* a, const uint32_t* b) {
    asm volatile("mma.sync.aligned.m16n8k16.row.col.f32.f16.f16.f32 "
                 "{%0,%1,%2,%3}, {%4,%5,%6,%7}, {%8,%9}, {%0,%1,%2,%3};"
                 : "+f"(c[0]), "+f"(c[1]), "+f"(c[2]), "+f"(c[3])
                 : "r"(a[0]), "r"(a[1]), "r"(a[2]), "r"(a[3]), "r"(b[0]), "r"(b[1]));
}
__device__ __forceinline__ uint32_t swz128(uint32_t o) { return o ^ ((o >> 3) & 0x70); }

// ---------------------------------------------------------------------------
// pad dtype detect (robust: bool-as-byte vs int32/float32 0/1)
// ---------------------------------------------------------------------------
__global__ void detect_pad_kernel(const unsigned char* __restrict__ pad) {
    __shared__ int s_gt1, s_off4;
    if (threadIdx.x == 0) { s_gt1 = 0; s_off4 = 0; }
    __syncthreads();
    for (int i = threadIdx.x; i < B_*ML_; i += blockDim.x) {
        unsigned char v = pad[i];
        if (v > 1) atomicOr(&s_gt1, 1);
        if (v != 0 && (i & 3) != 0) atomicOr(&s_off4, 1);
    }
    __syncthreads();
    if (threadIdx.x == 0)
        g_pad_byte_mode = (s_gt1 == 0 && s_off4 != 0) ? 1 : 0;
}

// ---------------------------------------------------------------------------
// Embedding gather -> fp16 A cols [0,1024) of gates GEMM
// ---------------------------------------------------------------------------
__global__ void gather_words_kernel(const int* __restrict__ tgt,
                                    const float* __restrict__ emb) {
    int idx = blockIdx.x * blockDim.x + threadIdx.x;
    if (idx >= B_*E_) return;
    int b = idx >> 10, e = idx & (E_ - 1);
    g_ag[b * KGATE + e] = __float2half_rn(emb[(long long)tgt[b] * E_ + e]);
}

// ---------------------------------------------------------------------------
// Attention; writes fp32 ctx (for LSTM) + fp16 ctx into gates-A cols [1024,2048)
// ---------------------------------------------------------------------------
__global__ void attn_kernel(const float* __restrict__ enc,
                            const float* __restrict__ h0,
                            const void* __restrict__ pad_raw) {
    int b = blockIdx.x;
    __shared__ float sh_h[E_];
    __shared__ float sh_w[ML_];
    int tid = threadIdx.x;
    for (int i = tid; i < E_; i += 256) sh_h[i] = h0[(long long)b*E_ + i];
    __syncthreads();
    int w = tid >> 5, lane = tid & 31;
    for (int l = w; l < ML_; l += 8) {
        const float* row = enc + ((long long)b*ML_ + l) * E_;
        float s = 0.f;
        for (int e = lane; e < E_; e += 32) s += row[e] * sh_h[e];
        #pragma unroll
        for (int o = 16; o > 0; o >>= 1) s += __shfl_down_sync(0xffffffffu, s, o);
        if (lane == 0) sh_w[l] = s;
    }
    __syncthreads();
    if (tid == 0) {
        int bm = g_pad_byte_mode;
        const unsigned char* p8 = (const unsigned char*)pad_raw;
        const unsigned int*  pw = (const unsigned int*)pad_raw;
        float mx = -1e30f;
        for (int l = 0; l < ML_; l++) mx = fmaxf(mx, sh_w[l]);
        float sum = 0.f;
        for (int l = 0; l < ML_; l++) {
            bool masked = bm ? (p8[b*ML_ + l] != 0) : (pw[b*ML_ + l] != 0u);
            float v = masked ? 0.f : __expf(sh_w[l] - mx);
            sh_w[l] = v; sum += v;
        }
        float inv = 1.f / sum;
        for (int l = 0; l < ML_; l++) sh_w[l] *= inv;
    }
    __syncthreads();
    for (int e = tid; e < E_; e += 256) {
        const float* base = enc + (long long)b*ML_*E_ + e;
        float acc = 0.f;
        #pragma unroll 10
        for (int l = 0; l < ML_; l++) acc += sh_w[l] * base[(long long)l*E_];
        g_ctx[(long long)b*E_ + e] = acc;
        g_ag[b * KGATE + E_ + e] = __float2half_rn(acc);
    }
}

// ---------------------------------------------------------------------------
// fp32 -> fp16 converters (8 elems/thread, 16B stores)
// ---------------------------------------------------------------------------
__global__ void conv_wproj_kernel(const float* __restrict__ src) {
    long long t = (long long)blockIdx.x * blockDim.x + threadIdx.x;
    const long long total = (long long)NPADV * (E_/8);
    if (t >= total) return;
    int row = (int)(t / (E_/8));
    int k0  = (int)(t % (E_/8)) * 8;
    H8 hi;
    if (row < V_) {
        const float4 a = *(const float4*)(src + (long long)row*E_ + k0);
        const float4 b = *(const float4*)(src + (long long)row*E_ + k0 + 4);
        hi.h[0]=__float2half_rn(a.x); hi.h[1]=__float2half_rn(a.y);
        hi.h[2]=__float2half_rn(a.z); hi.h[3]=__float2half_rn(a.w);
        hi.h[4]=__float2half_rn(b.x); hi.h[5]=__float2half_rn(b.y);
        hi.h[6]=__float2half_rn(b.z); hi.h[7]=__float2half_rn(b.w);
    } else {
        hi.u = make_uint4(0u, 0u, 0u, 0u);
    }
    *(uint4*)&g_wp[(long long)row * E_ + k0] = hi.u;
}

__global__ void conv_wgate_kernel(const float* __restrict__ w_ih,
                                  const float* __restrict__ w_hh) {
    long long t = (long long)blockIdx.x * blockDim.x + threadIdx.x;
    const long long total = (long long)G4E_ * (KGATE/8);
    if (t >= total) return;
    int row = (int)(t / (KGATE/8));
    int k0  = (int)(t % (KGATE/8)) * 8;
    const float* s = (k0 < E_) ? (w_ih + (long long)row*E_ + k0)
                               : (w_hh + (long long)row*E_ + (k0 - E_));
    const float4 a = *(const float4*)s;
    const float4 b = *(const float4*)(s + 4);
    H8 hi;
    hi.h[0]=__float2half_rn(a.x); hi.h[1]=__float2half_rn(a.y);
    hi.h[2]=__float2half_rn(a.z); hi.h[3]=__float2half_rn(a.w);
    hi.h[4]=__float2half_rn(b.x); hi.h[5]=__float2half_rn(b.y);
    hi.h[6]=__float2half_rn(b.z); hi.h[7]=__float2half_rn(b.w);
    *(uint4*)&g_wg[(long long)row * KGATE + k0] = hi.u;
}

// ---------------------------------------------------------------------------
// fp16 GEMM via mma.sync: C[M,N] = A[M,K2] * B[N,K2]^T (+bias)
// CTA BMx128, K-chunk 64, 3-stage cp.async pipeline, SW128 smem, ldmatrix.
// BM=128: warps 4(m)x2(n), warp tile 32x64. BM=64: warps 2(m)x4(n), 32x32.
// grid.x = m-blocks (fast) so CTAs sharing a B tile run concurrently.
// ---------------------------------------------------------------------------
template<int BM>
__global__ void __launch_bounds__(256, 2) gemm_fp16_mma(
    const __half* __restrict__ A2, const __half* __restrict__ B2,
    float* __restrict__ C, const float* __restrict__ bias,
    int K2, int Nreal)
{
    constexpr int WMW = (BM == 128) ? 4 : 2;       // warps along m
    constexpr int WNW = 8 / WMW;                   // warps along n
    constexpr int WN  = 128 / WNW;                 // n cols per warp
    constexpr int NT  = WN / 8;                    // n mma tiles per warp
    constexpr int ATILE = BM * 128;                // bytes
    constexpr int STAGE = ATILE + 16384;
    constexpr int OPS = (BM + 128) / 32;           // cp.async 16B ops per thread
    constexpr int OPSA = BM * 8;

    extern __shared__ char smem_raw[];
    const uint32_t smem = smem_u32(smem_raw);

    const int tid = threadIdx.x;
    const int wid = tid >> 5, lane = tid & 31;
    const int wm = wid % WMW, wn = wid / WMW;
    const int m0 = blockIdx.x * BM, n0 = blockIdx.y * 128;
    const int nch = K2 >> 6;

    const __half* Abase = A2 + (long long)m0 * K2;
    const __half* Bbase = B2 + (long long)n0 * K2;

    auto issue_stage = [&](int stage, int chunk) {
        int kc = chunk * 64;
        uint32_t sbase = smem + stage * STAGE;
        #pragma unroll
        for (int j = 0; j < OPS; j++) {
            int op = tid + j * 256;
            const __half* src;
            uint32_t dst;
            if (op < OPSA) {
                int row = op >> 3, c = op & 7;
                src = Abase + (long long)row * K2 + kc + c * 8;
                dst = sbase + swz128((uint32_t)(row * 128 + c * 16));
            } else {
                int op2 = op - OPSA;
                int row = op2 >> 3, c = op2 & 7;
                src = Bbase + (long long)row * K2 + kc + c * 8;
                dst = sbase + ATILE + swz128((uint32_t)(row * 128 + c * 16));
            }
            CP_ASYNC16(dst, (const void*)src);
        }
        CP_COMMIT();
    };

    float acc[2][NT][4];
    #pragma unroll
    for (int mt = 0; mt < 2; mt++)
        #pragma unroll
        for (int nt = 0; nt < NT; nt++)
            #pragma unroll
            for (int q = 0; q < 4; q++) acc[mt][nt][q] = 0.f;

    issue_stage(0, 0);
    if (nch > 1) issue_stage(1, 1); else CP_COMMIT();

    const int a_row_in = lane & 15;
    const int a_chunk  = lane >> 4;
    const int b_row_in = (lane & 7) + ((lane & 16) ? 8 : 0);
    const int b_chunk  = (lane >> 3) & 1;

    for (int i = 0; i < nch; i++) {
        CP_WAIT1();
        __syncthreads();
        if (i + 2 < nch) issue_stage((i + 2) % 3, i + 2);
        else CP_COMMIT();

        uint32_t sbase = smem + (i % 3) * STAGE;
        uint32_t As = sbase, Bs = sbase + ATILE;

        #pragma unroll
        for (int ks = 0; ks < 4; ks++) {
            uint32_t a[2][4];
            #pragma unroll
            for (int mt = 0; mt < 2; mt++) {
                int row = wm * 32 + mt * 16 + a_row_in;
                int ch  = ks * 2 + a_chunk;
                uint32_t addr = As + swz128((uint32_t)(row * 128 + ch * 16));
                ldsm_x4(addr, a[mt][0], a[mt][1], a[mt][2], a[mt][3]);
            }
            uint32_t b[NT][2];
            #pragma unroll
            for (int np = 0; np < NT/2; np++) {
                int row = wn * WN + np * 16 + b_row_in;
                int ch  = ks * 2 + b_chunk;
                uint32_t addr = Bs + swz128((uint32_t)(row * 128 + ch * 16));
                ldsm_x4(addr, b[np*2][0], b[np*2][1], b[np*2+1][0], b[np*2+1][1]);
            }
            #pragma unroll
            for (int mt = 0; mt < 2; mt++)
                #pragma unroll
                for (int nt = 0; nt < NT; nt++)
                    mma16816(acc[mt][nt], a[mt], b[nt]);
        }
        __syncthreads();
    }
    CP_WAIT0();

    #pragma unroll
    for (int mt = 0; mt < 2; mt++) {
        int r0g = m0 + wm * 32 + mt * 16 + (lane >> 2);
        #pragma unroll
        for (int nt = 0; nt < NT; nt++) {
            int col = n0 + wn * WN + nt * 8 + (lane & 3) * 2;
            if (col >= Nreal) continue;
            float bx = 0.f, by = 0.f;
            if (bias) { bx = bias[col]; by = bias[col + 1]; }
            float2 v0 = make_float2(acc[mt][nt][0] + bx, acc[mt][nt][1] + by);
            float2 v1 = make_float2(acc[mt][nt][2] + bx, acc[mt][nt][3] + by);
            *(float2*)(C + (long long)r0g * Nreal + col) = v0;
            *(float2*)(C + (long long)(r0g + 8) * Nreal + col) = v1;
        }
    }
}

// ---------------------------------------------------------------------------
// LSTM elementwise; also writes fp16 h for the logits GEMM A side
// ---------------------------------------------------------------------------
__global__ void lstm_kernel(const float* __restrict__ b_ih,
                            const float* __restrict__ b_hh,
                            float* __restrict__ h_out,
                            float* __restrict__ c_out) {
    int idx = blockIdx.x * blockDim.x + threadIdx.x;
    if (idx >= B_*E_) return;
    int b = idx >> 10, e = idx & (E_ - 1);
    const float* g = g_gates + (long long)b * G4E_;
    float xi = g[e]        + b_ih[e]        + b_hh[e];
    float xf = g[E_   + e] + b_ih[E_   + e] + b_hh[E_   + e];
    float xg = g[2*E_ + e] + b_ih[2*E_ + e] + b_hh[2*E_ + e];
    float xo = g[3*E_ + e] + b_ih[3*E_ + e] + b_hh[3*E_ + e];
    float ig = 1.f / (1.f + __expf(-xi));
    float fg = 1.f / (1.f + __expf(-xf));
    float gg = tanhf(xg);
    float og = 1.f / (1.f + __expf(-xo));
    float c  = fg * g_ctx[idx] + ig * gg;
    float h  = og * tanhf(c);
    h_out[idx] = h;
    c_out[idx] = c;
    g_h[idx] = __float2half_rn(h);
}

// ---------------------------------------------------------------------------
extern "C" void kernel_launch(void* const* d_in, const int* in_sizes, int n_in,
                              void* d_out, int out_size) {
    const void *p_tgt=0, *p_enc=0, *p_h0=0, *p_pad=0, *p_emb=0, *p_wproj=0,
               *p_wih=0, *p_whh=0, *p_bih=0, *p_bhh=0, *p_bproj=0;
    int seen_be = 0, seen_ve = 0, seen_w = 0, seen_b4 = 0;
    for (int i = 0; i < n_in; i++) {
        long long s = in_sizes[i];
        if      (s == 512)                  p_tgt = d_in[i];
        else if (s == (long long)B_*ML_*E_) p_enc = d_in[i];
        else if (s == (long long)B_*E_)     { if (seen_be++ == 0) p_h0 = d_in[i]; }
        else if (s == B_*ML_)               p_pad = d_in[i];
        else if (s == (long long)V_*E_)     { if (seen_ve++ == 0) p_emb = d_in[i]; else p_wproj = d_in[i]; }
        else if (s == (long long)G4E_*E_)   { if (seen_w++  == 0) p_wih = d_in[i]; else p_whh = d_in[i]; }
        else if (s == G4E_)                 { if (seen_b4++ == 0) p_bih = d_in[i]; else p_bhh = d_in[i]; }
        else if (s == V_)                   p_bproj = d_in[i];
    }

    const int*   tgt    = (const int*)p_tgt;
    const float* enc    = (const float*)p_enc;
    const float* h0     = (const float*)p_h0;
    const float* emb    = (const float*)p_emb;
    const float* w_ih   = (const float*)p_wih;
    const float* w_hh   = (const float*)p_whh;
    const float* b_ih   = (const float*)p_bih;
    const float* b_hh   = (const float*)p_bhh;
    const float* w_proj = (const float*)p_wproj;
    const float* b_proj = (const float*)p_bproj;

    float* out    = (float*)d_out;
    float* logits = out;
    float* h_out  = out + (long long)B_ * V_;
    float* c_out  = h_out + (long long)B_ * E_;

    float *gates;
    cudaGetSymbolAddress((void**)&gates, g_gates);
    __half *wp, *wg, *ag, *hh;
    cudaGetSymbolAddress((void**)&wp, g_wp);
    cudaGetSymbolAddress((void**)&wg, g_wg);
    cudaGetSymbolAddress((void**)&ag, g_ag);
    cudaGetSymbolAddress((void**)&hh, g_h);

    const int SMEM128 = 3 * (128*128 + 16384);   // 96 KB
    const int SMEM64  = 3 * (64*128 + 16384);    // 72 KB
    cudaFuncSetAttribute(gemm_fp16_mma<128>, cudaFuncAttributeMaxDynamicSharedMemorySize, SMEM128);
    cudaFuncSetAttribute(gemm_fp16_mma<64>,  cudaFuncAttributeMaxDynamicSharedMemorySize, SMEM64);

    detect_pad_kernel<<<1, 1024>>>((const unsigned char*)p_pad);
    gather_words_kernel<<<(B_*E_ + 255)/256, 256>>>(tgt, emb);
    attn_kernel<<<B_, 256>>>(enc, h0, p_pad);

    {
        long long tg = (long long)G4E_ * (KGATE/8);
        conv_wgate_kernel<<<(unsigned)((tg + 255)/256), 256>>>(w_ih, w_hh);
    }

    // gates GEMM: [512,2048] x [4096,2048]^T -> g_gates  (BM=64 -> 256 CTAs)
    {
        dim3 grid(B_/64, G4E_/128);
        gemm_fp16_mma<64><<<grid, 256, SMEM64>>>(ag, wg, gates, nullptr, KGATE, G4E_);
    }

    lstm_kernel<<<(B_*E_ + 255)/256, 256>>>(b_ih, b_hh, h_out, c_out);

    {
        long long tot = (long long)NPADV * (E_/8);
        conv_wproj_kernel<<<(unsigned)((tot + 255)/256), 256>>>(w_proj);
    }

    // logits GEMM: [512,1024] x [50048,1024]^T -> logits (+b_proj)
    {
        dim3 grid(B_/128, NPADV/128);
        gemm_fp16_mma<128><<<grid, 256, SMEM128>>>(hh, wp, logits, b_proj, E_, V_);
    }
}

// round 10
// speedup vs baseline: 1.9345x; 1.3901x over previous
#include <cuda_runtime.h>
#include <cuda_fp16.h>
#include <math.h>
#include <stdint.h>

#define B_    512
#define E_    1024
#define ML_   50
#define V_    50000
#define G4E_  (4*E_)
#define KGATE 2048           // gates K: [words|ctx] vs [w_ih|w_hh]

// ---------------- scratch (__device__ globals; allocation-free rule) --------
__device__ float g_ctx[B_*E_];
__device__ float g_gates[(long long)B_*G4E_];
__device__ int   g_pad_byte_mode;
__device__ __half g_ag[B_*KGATE];                // [words | ctx] fp16 (GEMM A)
__device__ __half g_h[B_*E_];                    // h_new fp16 (GEMM A)

// ---------------- PTX helpers (arch-stable, sm_80-era) ----------------------
__device__ __forceinline__ uint32_t smem_u32(const void* p) {
    uint32_t a;
    asm("{ .reg .u64 t; cvta.to.shared.u64 t, %1; cvt.u32.u64 %0, t; }" : "=r"(a) : "l"(p));
    return a;
}
#define CP_ASYNC16(dst, src) \
    asm volatile("cp.async.cg.shared.global [%0], [%1], 16;" :: "r"(dst), "l"(src) : "memory")
#define CP_COMMIT() asm volatile("cp.async.commit_group;" ::: "memory")
#define CP_WAIT1()  asm volatile("cp.async.wait_group 1;" ::: "memory")
#define CP_WAIT0()  asm volatile("cp.async.wait_group 0;" ::: "memory")

__device__ __forceinline__ void ldsm_x4(uint32_t addr, uint32_t& r0, uint32_t& r1,
                                        uint32_t& r2, uint32_t& r3) {
    asm volatile("ldmatrix.sync.aligned.m8n8.x4.shared.b16 {%0,%1,%2,%3}, [%4];"
                 : "=r"(r0), "=r"(r1), "=r"(r2), "=r"(r3) : "r"(addr));
}
__device__ __forceinline__ void mma16816(float* c, const uint32_t* a, const uint32_t* b) {
    asm volatile("mma.sync.aligned.m16n8k16.row.col.f32.f16.f16.f32 "
                 "{%0,%1,%2,%3}, {%4,%5,%6,%7}, {%8,%9}, {%0,%1,%2,%3};"
                 : "+f"(c[0]), "+f"(c[1]), "+f"(c[2]), "+f"(c[3])
                 : "r"(a[0]), "r"(a[1]), "r"(a[2]), "r"(a[3]), "r"(b[0]), "r"(b[1]));
}
__device__ __forceinline__ uint32_t swz128(uint32_t o) { return o ^ ((o >> 3) & 0x70); }
__device__ __forceinline__ uint32_t swz64 (uint32_t o) { return o ^ ((o >> 3) & 0x30); }

// ---------------------------------------------------------------------------
// pad dtype detect (robust: bool-as-byte vs int32/float32 0/1)
// ---------------------------------------------------------------------------
__global__ void detect_pad_kernel(const unsigned char* __restrict__ pad) {
    __shared__ int s_gt1, s_off4;
    if (threadIdx.x == 0) { s_gt1 = 0; s_off4 = 0; }
    __syncthreads();
    for (int i = threadIdx.x; i < B_*ML_; i += blockDim.x) {
        unsigned char v = pad[i];
        if (v > 1) atomicOr(&s_gt1, 1);
        if (v != 0 && (i & 3) != 0) atomicOr(&s_off4, 1);
    }
    __syncthreads();
    if (threadIdx.x == 0)
        g_pad_byte_mode = (s_gt1 == 0 && s_off4 != 0) ? 1 : 0;
}

// ---------------------------------------------------------------------------
// Embedding gather -> fp16 A cols [0,1024), 4 elems/thread
// ---------------------------------------------------------------------------
__global__ void gather_words_kernel(const int* __restrict__ tgt,
                                    const float* __restrict__ emb) {
    int t = blockIdx.x * blockDim.x + threadIdx.x;
    if (t >= B_*(E_/4)) return;
    int b = t / (E_/4), e4 = t % (E_/4);
    float4 v = *(const float4*)(emb + (long long)tgt[b] * E_ + e4*4);
    __half2 h01 = __floats2half2_rn(v.x, v.y);
    __half2 h23 = __floats2half2_rn(v.z, v.w);
    uint2 u = make_uint2(*(uint32_t*)&h01, *(uint32_t*)&h23);
    *(uint2*)&g_ag[b * KGATE + e4*4] = u;
}

// ---------------------------------------------------------------------------
// Attention (vectorized); fp32 ctx for LSTM + fp16 ctx into A cols [1024,2048)
// ---------------------------------------------------------------------------
__global__ void attn_kernel(const float* __restrict__ enc,
                            const float* __restrict__ h0,
                            const void* __restrict__ pad_raw) {
    int b = blockIdx.x;
    __shared__ float4 sh_h4[E_/4];
    __shared__ float sh_w[ML_];
    int tid = threadIdx.x;
    const float4* h04 = (const float4*)(h0 + (long long)b*E_);
    if (tid < 256) sh_h4[tid] = h04[tid];
    __syncthreads();
    int w = tid >> 5, lane = tid & 31;
    for (int l = w; l < ML_; l += 8) {
        const float4* row4 = (const float4*)(enc + ((long long)b*ML_ + l) * E_);
        float s = 0.f;
        #pragma unroll
        for (int j = 0; j < 8; j++) {
            float4 x = row4[lane + j*32];
            float4 h = sh_h4[lane + j*32];
            s += x.x*h.x + x.y*h.y + x.z*h.z + x.w*h.w;
        }
        #pragma unroll
        for (int o = 16; o > 0; o >>= 1) s += __shfl_down_sync(0xffffffffu, s, o);
        if (lane == 0) sh_w[l] = s;
    }
    __syncthreads();
    if (tid == 0) {
        int bm = g_pad_byte_mode;
        const unsigned char* p8 = (const unsigned char*)pad_raw;
        const unsigned int*  pw = (const unsigned int*)pad_raw;
        float mx = -1e30f;
        for (int l = 0; l < ML_; l++) mx = fmaxf(mx, sh_w[l]);
        float sum = 0.f;
        for (int l = 0; l < ML_; l++) {
            bool masked = bm ? (p8[b*ML_ + l] != 0) : (pw[b*ML_ + l] != 0u);
            float v = masked ? 0.f : __expf(sh_w[l] - mx);
            sh_w[l] = v; sum += v;
        }
        float inv = 1.f / sum;
        for (int l = 0; l < ML_; l++) sh_w[l] *= inv;
    }
    __syncthreads();
    // context: 256 threads x 1 float4-column each
    if (tid < 256) {
        const float4* base = (const float4*)enc + (long long)b*ML_*(E_/4) + tid;
        float4 acc = make_float4(0.f, 0.f, 0.f, 0.f);
        #pragma unroll 10
        for (int l = 0; l < ML_; l++) {
            float wl = sh_w[l];
            float4 v = base[l * (E_/4)];
            acc.x += wl*v.x; acc.y += wl*v.y; acc.z += wl*v.z; acc.w += wl*v.w;
        }
        *(float4*)(g_ctx + (long long)b*E_ + tid*4) = acc;
        __half2 h01 = __floats2half2_rn(acc.x, acc.y);
        __half2 h23 = __floats2half2_rn(acc.z, acc.w);
        uint2 u = make_uint2(*(uint32_t*)&h01, *(uint32_t*)&h23);
        *(uint2*)&g_ag[b * KGATE + E_ + tid*4] = u;
    }
}

// ---------------------------------------------------------------------------
// GEMM, fp16 A x fp32 B (converted in-smem): C[M,N] = A*B^T (+bias)
// K-chunk = 32. Per stage: A fp16 tile (BM x 64B), B fp16 tile (128 x 64B),
// B fp32 tile (128 x 128B). cp.async streams A(fp16) + B(fp32); a convert
// phase (LDS fp32 -> cvt -> STS fp16) feeds the ldmatrix/mma consumer.
// 3 stages. B optionally segmented [B0|B1] at float offset ksplit.
// BM=128: warps 4m x 2n (32x64). BM=64: warps 2m x 4n (32x32).
// ---------------------------------------------------------------------------
template<int BM>
__global__ void __launch_bounds__(256, 2) gemm_f32b(
    const __half* __restrict__ A,
    const float* __restrict__ B0, const float* __restrict__ B1, int ksplit,
    int bstride, int nbrows,
    float* __restrict__ C, const float* __restrict__ bias,
    int K, int Nreal)
{
    constexpr int WMW = (BM == 128) ? 4 : 2;
    constexpr int WNW = 8 / WMW;
    constexpr int WN  = 128 / WNW;
    constexpr int NT  = WN / 8;
    constexpr int AT_B   = BM * 64;                 // A fp16 tile bytes
    constexpr int BH_B   = 128 * 64;                // B fp16 tile bytes
    constexpr int BF_B   = 128 * 128;               // B fp32 tile bytes
    constexpr int STAGE  = AT_B + BH_B + BF_B;
    constexpr int AOPS   = BM * 4 / 256;            // A cp.async per thread
    extern __shared__ char smem_raw[];
    const uint32_t smem = smem_u32(smem_raw);

    const int tid = threadIdx.x;
    const int wid = tid >> 5, lane = tid & 31;
    const int wm = wid % WMW, wn = wid / WMW;
    const int m0 = blockIdx.x * BM, n0 = blockIdx.y * 128;
    const int nch = K >> 5;                          // 32-elem chunks

    auto issue_stage = [&](int stage, int chunk) {
        int kc = chunk * 32;
        uint32_t sb = smem + stage * STAGE;
        #pragma unroll
        for (int j = 0; j < AOPS; j++) {             // A fp16: 16B x BM*4 ops
            int op = tid + j * 256;
            int row = op >> 2, c = op & 3;
            const __half* src = A + (long long)(m0 + row) * K + kc + c * 8;
            CP_ASYNC16(sb + swz64((uint32_t)(row * 64 + c * 16)), (const void*)src);
        }
        const float* bp; int kb;
        if (kc < ksplit) { bp = B0; kb = kc; } else { bp = B1; kb = kc - ksplit; }
        #pragma unroll
        for (int j = 0; j < 4; j++) {                // B fp32: 16B x 1024 ops
            int op = tid + j * 256;
            int row = op >> 3, c = op & 7;
            int gn = n0 + row; if (gn >= nbrows) gn = nbrows - 1;
            const float* src = bp + (long long)gn * bstride + kb + c * 4;
            CP_ASYNC16(sb + AT_B + BH_B + swz128((uint32_t)(row * 128 + c * 16)),
                       (const void*)src);
        }
        CP_COMMIT();
    };

    float acc[2][NT][4];
    #pragma unroll
    for (int mt = 0; mt < 2; mt++)
        #pragma unroll
        for (int nt = 0; nt < NT; nt++)
            #pragma unroll
            for (int q = 0; q < 4; q++) acc[mt][nt][q] = 0.f;

    issue_stage(0, 0);
    if (nch > 1) issue_stage(1, 1); else CP_COMMIT();

    const int a_row_in = lane & 15;
    const int a_chunk  = lane >> 4;
    const int b_row_in = (lane & 7) + ((lane & 16) ? 8 : 0);
    const int b_chunk  = (lane >> 3) & 1;
    const int cr = tid >> 1, chh = tid & 1;          // convert-phase mapping

    for (int i = 0; i < nch; i++) {
        CP_WAIT1();
        __syncthreads();

        uint32_t sb = smem + (i % 3) * STAGE;
        uint32_t As = sb, Bs = sb + AT_B, Bf = sb + AT_B + BH_B;

        // ---- convert: B fp32 (128x128B) -> B fp16 (128x64B) ----
        {
            float4 v0 = *(const float4*)(smem_raw + (Bf - smem) + swz128((uint32_t)(cr*128 + chh*64)));
            float4 v1 = *(const float4*)(smem_raw + (Bf - smem) + swz128((uint32_t)(cr*128 + chh*64 + 16)));
            float4 v2 = *(const float4*)(smem_raw + (Bf - smem) + swz128((uint32_t)(cr*128 + chh*64 + 32)));
            float4 v3 = *(const float4*)(smem_raw + (Bf - smem) + swz128((uint32_t)(cr*128 + chh*64 + 48)));
            __half2 h0 = __floats2half2_rn(v0.x, v0.y), h1 = __floats2half2_rn(v0.z, v0.w);
            __half2 h2 = __floats2half2_rn(v1.x, v1.y), h3 = __floats2half2_rn(v1.z, v1.w);
            __half2 h4 = __floats2half2_rn(v2.x, v2.y), h5 = __floats2half2_rn(v2.z, v2.w);
            __half2 h6 = __floats2half2_rn(v3.x, v3.y), h7 = __floats2half2_rn(v3.z, v3.w);
            uint4 u0 = make_uint4(*(uint32_t*)&h0, *(uint32_t*)&h1, *(uint32_t*)&h2, *(uint32_t*)&h3);
            uint4 u1 = make_uint4(*(uint32_t*)&h4, *(uint32_t*)&h5, *(uint32_t*)&h6, *(uint32_t*)&h7);
            *(uint4*)(smem_raw + (Bs - smem) + swz64((uint32_t)(cr*64 + chh*32)))      = u0;
            *(uint4*)(smem_raw + (Bs - smem) + swz64((uint32_t)(cr*64 + chh*32 + 16))) = u1;
        }
        __syncthreads();

        if (i + 2 < nch) issue_stage((i + 2) % 3, i + 2);
        else CP_COMMIT();

        // ---- mma: 2 ks-steps of K=16 ----
        #pragma unroll
        for (int ks = 0; ks < 2; ks++) {
            uint32_t a[2][4];
            #pragma unroll
            for (int mt = 0; mt < 2; mt++) {
                int row = wm * 32 + mt * 16 + a_row_in;
                int ch  = ks * 2 + a_chunk;
                ldsm_x4(As + swz64((uint32_t)(row * 64 + ch * 16)),
                        a[mt][0], a[mt][1], a[mt][2], a[mt][3]);
            }
            uint32_t b[NT][2];
            #pragma unroll
            for (int np = 0; np < NT/2; np++) {
                int row = wn * WN + np * 16 + b_row_in;
                int ch  = ks * 2 + b_chunk;
                ldsm_x4(Bs + swz64((uint32_t)(row * 64 + ch * 16)),
                        b[np*2][0], b[np*2][1], b[np*2+1][0], b[np*2+1][1]);
            }
            #pragma unroll
            for (int mt = 0; mt < 2; mt++)
                #pragma unroll
                for (int nt = 0; nt < NT; nt++)
                    mma16816(acc[mt][nt], a[mt], b[nt]);
        }
        __syncthreads();
    }
    CP_WAIT0();

    #pragma unroll
    for (int mt = 0; mt < 2; mt++) {
        int r0g = m0 + wm * 32 + mt * 16 + (lane >> 2);
        #pragma unroll
        for (int nt = 0; nt < NT; nt++) {
            int col = n0 + wn * WN + nt * 8 + (lane & 3) * 2;
            if (col >= Nreal) continue;
            float bx = 0.f, by = 0.f;
            if (bias) { bx = bias[col]; by = bias[col + 1]; }
            float2 v0 = make_float2(acc[mt][nt][0] + bx, acc[mt][nt][1] + by);
            float2 v1 = make_float2(acc[mt][nt][2] + bx, acc[mt][nt][3] + by);
            *(float2*)(C + (long long)r0g * Nreal + col) = v0;
            *(float2*)(C + (long long)(r0g + 8) * Nreal + col) = v1;
        }
    }
}

// ---------------------------------------------------------------------------
// LSTM elementwise; also writes fp16 h for the logits GEMM A side
// ---------------------------------------------------------------------------
__global__ void lstm_kernel(const float* __restrict__ b_ih,
                            const float* __restrict__ b_hh,
                            float* __restrict__ h_out,
                            float* __restrict__ c_out) {
    int idx = blockIdx.x * blockDim.x + threadIdx.x;
    if (idx >= B_*E_) return;
    int b = idx >> 10, e = idx & (E_ - 1);
    const float* g = g_gates + (long long)b * G4E_;
    float xi = g[e]        + b_ih[e]        + b_hh[e];
    float xf = g[E_   + e] + b_ih[E_   + e] + b_hh[E_   + e];
    float xg = g[2*E_ + e] + b_ih[2*E_ + e] + b_hh[2*E_ + e];
    float xo = g[3*E_ + e] + b_ih[3*E_ + e] + b_hh[3*E_ + e];
    float ig = 1.f / (1.f + __expf(-xi));
    float fg = 1.f / (1.f + __expf(-xf));
    float gg = tanhf(xg);
    float og = 1.f / (1.f + __expf(-xo));
    float c  = fg * g_ctx[idx] + ig * gg;
    float h  = og * tanhf(c);
    h_out[idx] = h;
    c_out[idx] = c;
    g_h[idx] = __float2half_rn(h);
}

// ---------------------------------------------------------------------------
extern "C" void kernel_launch(void* const* d_in, const int* in_sizes, int n_in,
                              void* d_out, int out_size) {
    const void *p_tgt=0, *p_enc=0, *p_h0=0, *p_pad=0, *p_emb=0, *p_wproj=0,
               *p_wih=0, *p_whh=0, *p_bih=0, *p_bhh=0, *p_bproj=0;
    int seen_be = 0, seen_ve = 0, seen_w = 0, seen_b4 = 0;
    for (int i = 0; i < n_in; i++) {
        long long s = in_sizes[i];
        if      (s == 512)                  p_tgt = d_in[i];
        else if (s == (long long)B_*ML_*E_) p_enc = d_in[i];
        else if (s == (long long)B_*E_)     { if (seen_be++ == 0) p_h0 = d_in[i]; }
        else if (s == B_*ML_)               p_pad = d_in[i];
        else if (s == (long long)V_*E_)     { if (seen_ve++ == 0) p_emb = d_in[i]; else p_wproj = d_in[i]; }
        else if (s == (long long)G4E_*E_)   { if (seen_w++  == 0) p_wih = d_in[i]; else p_whh = d_in[i]; }
        else if (s == G4E_)                 { if (seen_b4++ == 0) p_bih = d_in[i]; else p_bhh = d_in[i]; }
        else if (s == V_)                   p_bproj = d_in[i];
    }

    const int*   tgt    = (const int*)p_tgt;
    const float* enc    = (const float*)p_enc;
    const float* h0     = (const float*)p_h0;
    const float* emb    = (const float*)p_emb;
    const float* w_ih   = (const float*)p_wih;
    const float* w_hh   = (const float*)p_whh;
    const float* b_ih   = (const float*)p_bih;
    const float* b_hh   = (const float*)p_bhh;
    const float* w_proj = (const float*)p_wproj;
    const float* b_proj = (const float*)p_bproj;

    float* out    = (float*)d_out;
    float* logits = out;
    float* h_out  = out + (long long)B_ * V_;
    float* c_out  = h_out + (long long)B_ * E_;

    float *gates;
    cudaGetSymbolAddress((void**)&gates, g_gates);
    __half *ag, *hh;
    cudaGetSymbolAddress((void**)&ag, g_ag);
    cudaGetSymbolAddress((void**)&hh, g_h);

    const int SMEM128 = 3 * (128*64 + 128*64 + 128*128);   // 96 KB
    const int SMEM64  = 3 * (64*64  + 128*64 + 128*128);   // 84 KB
    cudaFuncSetAttribute(gemm_f32b<128>, cudaFuncAttributeMaxDynamicSharedMemorySize, SMEM128);
    cudaFuncSetAttribute(gemm_f32b<64>,  cudaFuncAttributeMaxDynamicSharedMemorySize, SMEM64);

    detect_pad_kernel<<<1, 1024>>>((const unsigned char*)p_pad);
    gather_words_kernel<<<(B_*(E_/4) + 255)/256, 256>>>(tgt, emb);
    attn_kernel<<<B_, 256>>>(enc, h0, p_pad);

    // gates GEMM: A=g_ag [512,2048] fp16; B=[w_ih|w_hh] fp32 split at 1024
    {
        dim3 grid(B_/64, G4E_/128);
        gemm_f32b<64><<<grid, 256, SMEM64>>>(
            ag, w_ih, w_hh, E_, E_, G4E_, gates, nullptr, KGATE, G4E_);
    }

    lstm_kernel<<<(B_*E_ + 255)/256, 256>>>(b_ih, b_hh, h_out, c_out);

    // logits GEMM: A=g_h [512,1024] fp16; B=w_proj fp32 [50000,1024]
    {
        dim3 grid(B_/128, (V_ + 127)/128);
        gemm_f32b<128><<<grid, 256, SMEM128>>>(
            hh, w_proj, w_proj, E_, E_, V_, logits, b_proj, E_, V_);
    }
}

// round 11
// speedup vs baseline: 1.9946x; 1.0310x over previous
#include <cuda_runtime.h>
#include <cuda_fp16.h>
#include <math.h>
#include <stdint.h>

#define B_    512
#define E_    1024
#define ML_   50
#define V_    50000
#define G4E_  (4*E_)
#define NPADV 50048          // V padded to multiple of 128
#define KGATE 2048           // gates K: [words|ctx] vs [w_ih|w_hh]

// ---------------- scratch (__device__ globals; allocation-free rule) --------
__device__ float g_ctx[B_*E_];
__device__ float g_gates[(long long)B_*G4E_];
__device__ int   g_pad_byte_mode;

__device__ __half g_wp[(long long)NPADV*E_];     // w_proj fp16 (rows >= V_ zero)
__device__ __half g_wg[(long long)G4E_*KGATE];   // [w_ih | w_hh] fp16
__device__ __half g_ag[B_*KGATE];                // [words | ctx] fp16 (GEMM A)
__device__ __half g_h[B_*E_];                    // h_new fp16 (GEMM A)

union H8 { __half h[8]; uint4 u; };

// ---------------- PTX helpers (arch-stable, sm_80-era) ----------------------
__device__ __forceinline__ uint32_t smem_u32(const void* p) {
    uint32_t a;
    asm("{ .reg .u64 t; cvta.to.shared.u64 t, %1; cvt.u32.u64 %0, t; }" : "=r"(a) : "l"(p));
    return a;
}
#define CP_ASYNC16(dst, src) \
    asm volatile("cp.async.cg.shared.global [%0], [%1], 16;" :: "r"(dst), "l"(src) : "memory")
#define CP_COMMIT() asm volatile("cp.async.commit_group;" ::: "memory")
#define CP_WAIT1()  asm volatile("cp.async.wait_group 1;" ::: "memory")
#define CP_WAIT0()  asm volatile("cp.async.wait_group 0;" ::: "memory")

__device__ __forceinline__ void ldsm_x4(uint32_t addr, uint32_t& r0, uint32_t& r1,
                                        uint32_t& r2, uint32_t& r3) {
    asm volatile("ldmatrix.sync.aligned.m8n8.x4.shared.b16 {%0,%1,%2,%3}, [%4];"
                 : "=r"(r0), "=r"(r1), "=r"(r2), "=r"(r3) : "r"(addr));
}
__device__ __forceinline__ void mma16816(float* c, const uint32_t* a, const uint32_t* b) {
    asm volatile("mma.sync.aligned.m16n8k16.row.col.f32.f16.f16.f32 "
                 "{%0,%1,%2,%3}, {%4,%5,%6,%7}, {%8,%9}, {%0,%1,%2,%3};"
                 : "+f"(c[0]), "+f"(c[1]), "+f"(c[2]), "+f"(c[3])
                 : "r"(a[0]), "r"(a[1]), "r"(a[2]), "r"(a[3]), "r"(b[0]), "r"(b[1]));
}
__device__ __forceinline__ uint32_t swz128(uint32_t o) { return o ^ ((o >> 3) & 0x70); }

// ---------------------------------------------------------------------------
// pad dtype detect (robust: bool-as-byte vs int32/float32 0/1)
// ---------------------------------------------------------------------------
__global__ void detect_pad_kernel(const unsigned char* __restrict__ pad) {
    __shared__ int s_gt1, s_off4;
    if (threadIdx.x == 0) { s_gt1 = 0; s_off4 = 0; }
    __syncthreads();
    for (int i = threadIdx.x; i < B_*ML_; i += blockDim.x) {
        unsigned char v = pad[i];
        if (v > 1) atomicOr(&s_gt1, 1);
        if (v != 0 && (i & 3) != 0) atomicOr(&s_off4, 1);
    }
    __syncthreads();
    if (threadIdx.x == 0)
        g_pad_byte_mode = (s_gt1 == 0 && s_off4 != 0) ? 1 : 0;
}

// ---------------------------------------------------------------------------
// Embedding gather -> fp16 A cols [0,1024), 4 elems/thread
// ---------------------------------------------------------------------------
__global__ void gather_words_kernel(const int* __restrict__ tgt,
                                    const float* __restrict__ emb) {
    int t = blockIdx.x * blockDim.x + threadIdx.x;
    if (t >= B_*(E_/4)) return;
    int b = t / (E_/4), e4 = t % (E_/4);
    float4 v = *(const float4*)(emb + (long long)tgt[b] * E_ + e4*4);
    __half2 h01 = __floats2half2_rn(v.x, v.y);
    __half2 h23 = __floats2half2_rn(v.z, v.w);
    uint2 u = make_uint2(*(uint32_t*)&h01, *(uint32_t*)&h23);
    *(uint2*)&g_ag[b * KGATE + e4*4] = u;
}

// ---------------------------------------------------------------------------
// Attention (vectorized); fp32 ctx for LSTM + fp16 ctx into A cols [1024,2048)
// ---------------------------------------------------------------------------
__global__ void attn_kernel(const float* __restrict__ enc,
                            const float* __restrict__ h0,
                            const void* __restrict__ pad_raw) {
    int b = blockIdx.x;
    __shared__ float4 sh_h4[E_/4];
    __shared__ float sh_w[ML_];
    int tid = threadIdx.x;
    const float4* h04 = (const float4*)(h0 + (long long)b*E_);
    if (tid < 256) sh_h4[tid] = h04[tid];
    __syncthreads();
    int w = tid >> 5, lane = tid & 31;
    for (int l = w; l < ML_; l += 8) {
        const float4* row4 = (const float4*)(enc + ((long long)b*ML_ + l) * E_);
        float s = 0.f;
        #pragma unroll
        for (int j = 0; j < 8; j++) {
            float4 x = row4[lane + j*32];
            float4 h = sh_h4[lane + j*32];
            s += x.x*h.x + x.y*h.y + x.z*h.z + x.w*h.w;
        }
        #pragma unroll
        for (int o = 16; o > 0; o >>= 1) s += __shfl_down_sync(0xffffffffu, s, o);
        if (lane == 0) sh_w[l] = s;
    }
    __syncthreads();
    if (tid == 0) {
        int bm = g_pad_byte_mode;
        const unsigned char* p8 = (const unsigned char*)pad_raw;
        const unsigned int*  pw = (const unsigned int*)pad_raw;
        float mx = -1e30f;
        for (int l = 0; l < ML_; l++) mx = fmaxf(mx, sh_w[l]);
        float sum = 0.f;
        for (int l = 0; l < ML_; l++) {
            bool masked = bm ? (p8[b*ML_ + l] != 0) : (pw[b*ML_ + l] != 0u);
            float v = masked ? 0.f : __expf(sh_w[l] - mx);
            sh_w[l] = v; sum += v;
        }
        float inv = 1.f / sum;
        for (int l = 0; l < ML_; l++) sh_w[l] *= inv;
    }
    __syncthreads();
    if (tid < 256) {
        const float4* base = (const float4*)enc + (long long)b*ML_*(E_/4) + tid;
        float4 acc = make_float4(0.f, 0.f, 0.f, 0.f);
        #pragma unroll 10
        for (int l = 0; l < ML_; l++) {
            float wl = sh_w[l];
            float4 v = base[l * (E_/4)];
            acc.x += wl*v.x; acc.y += wl*v.y; acc.z += wl*v.z; acc.w += wl*v.w;
        }
        *(float4*)(g_ctx + (long long)b*E_ + tid*4) = acc;
        __half2 h01 = __floats2half2_rn(acc.x, acc.y);
        __half2 h23 = __floats2half2_rn(acc.z, acc.w);
        uint2 u = make_uint2(*(uint32_t*)&h01, *(uint32_t*)&h23);
        *(uint2*)&g_ag[b * KGATE + E_ + tid*4] = u;
    }
}

// ---------------------------------------------------------------------------
// fp32 -> fp16 weight converters (run on the SIDE stream, overlapped)
// ---------------------------------------------------------------------------
__global__ void conv_wproj_kernel(const float* __restrict__ src) {
    long long t = (long long)blockIdx.x * blockDim.x + threadIdx.x;
    const long long total = (long long)NPADV * (E_/8);
    if (t >= total) return;
    int row = (int)(t / (E_/8));
    int k0  = (int)(t % (E_/8)) * 8;
    H8 hi;
    if (row < V_) {
        const float4 a = *(const float4*)(src + (long long)row*E_ + k0);
        const float4 b = *(const float4*)(src + (long long)row*E_ + k0 + 4);
        hi.h[0]=__float2half_rn(a.x); hi.h[1]=__float2half_rn(a.y);
        hi.h[2]=__float2half_rn(a.z); hi.h[3]=__float2half_rn(a.w);
        hi.h[4]=__float2half_rn(b.x); hi.h[5]=__float2half_rn(b.y);
        hi.h[6]=__float2half_rn(b.z); hi.h[7]=__float2half_rn(b.w);
    } else {
        hi.u = make_uint4(0u, 0u, 0u, 0u);
    }
    *(uint4*)&g_wp[(long long)row * E_ + k0] = hi.u;
}

__global__ void conv_wgate_kernel(const float* __restrict__ w_ih,
                                  const float* __restrict__ w_hh) {
    long long t = (long long)blockIdx.x * blockDim.x + threadIdx.x;
    const long long total = (long long)G4E_ * (KGATE/8);
    if (t >= total) return;
    int row = (int)(t / (KGATE/8));
    int k0  = (int)(t % (KGATE/8)) * 8;
    const float* s = (k0 < E_) ? (w_ih + (long long)row*E_ + k0)
                               : (w_hh + (long long)row*E_ + (k0 - E_));
    const float4 a = *(const float4*)s;
    const float4 b = *(const float4*)(s + 4);
    H8 hi;
    hi.h[0]=__float2half_rn(a.x); hi.h[1]=__float2half_rn(a.y);
    hi.h[2]=__float2half_rn(a.z); hi.h[3]=__float2half_rn(a.w);
    hi.h[4]=__float2half_rn(b.x); hi.h[5]=__float2half_rn(b.y);
    hi.h[6]=__float2half_rn(b.z); hi.h[7]=__float2half_rn(b.w);
    *(uint4*)&g_wg[(long long)row * KGATE + k0] = hi.u;
}

// ---------------------------------------------------------------------------
// fp16 GEMM via mma.sync (R9, proven): C[M,N] = A[M,K2] * B[N,K2]^T (+bias)
// CTA BMx128, K-chunk 64, 3-stage cp.async pipeline, SW128 smem, ldmatrix.
// ---------------------------------------------------------------------------
template<int BM>
__global__ void __launch_bounds__(256, 2) gemm_fp16_mma(
    const __half* __restrict__ A2, const __half* __restrict__ B2,
    float* __restrict__ C, const float* __restrict__ bias,
    int K2, int Nreal)
{
    constexpr int WMW = (BM == 128) ? 4 : 2;
    constexpr int WNW = 8 / WMW;
    constexpr int WN  = 128 / WNW;
    constexpr int NT  = WN / 8;
    constexpr int ATILE = BM * 128;
    constexpr int STAGE = ATILE + 16384;
    constexpr int OPS = (BM + 128) / 32;
    constexpr int OPSA = BM * 8;

    extern __shared__ char smem_raw[];
    const uint32_t smem = smem_u32(smem_raw);

    const int tid = threadIdx.x;
    const int wid = tid >> 5, lane = tid & 31;
    const int wm = wid % WMW, wn = wid / WMW;
    const int m0 = blockIdx.x * BM, n0 = blockIdx.y * 128;
    const int nch = K2 >> 6;

    const __half* Abase = A2 + (long long)m0 * K2;
    const __half* Bbase = B2 + (long long)n0 * K2;

    auto issue_stage = [&](int stage, int chunk) {
        int kc = chunk * 64;
        uint32_t sbase = smem + stage * STAGE;
        #pragma unroll
        for (int j = 0; j < OPS; j++) {
            int op = tid + j * 256;
            const __half* src;
            uint32_t dst;
            if (op < OPSA) {
                int row = op >> 3, c = op & 7;
                src = Abase + (long long)row * K2 + kc + c * 8;
                dst = sbase + swz128((uint32_t)(row * 128 + c * 16));
            } else {
                int op2 = op - OPSA;
                int row = op2 >> 3, c = op2 & 7;
                src = Bbase + (long long)row * K2 + kc + c * 8;
                dst = sbase + ATILE + swz128((uint32_t)(row * 128 + c * 16));
            }
            CP_ASYNC16(dst, (const void*)src);
        }
        CP_COMMIT();
    };

    float acc[2][NT][4];
    #pragma unroll
    for (int mt = 0; mt < 2; mt++)
        #pragma unroll
        for (int nt = 0; nt < NT; nt++)
            #pragma unroll
            for (int q = 0; q < 4; q++) acc[mt][nt][q] = 0.f;

    issue_stage(0, 0);
    if (nch > 1) issue_stage(1, 1); else CP_COMMIT();

    const int a_row_in = lane & 15;
    const int a_chunk  = lane >> 4;
    const int b_row_in = (lane & 7) + ((lane & 16) ? 8 : 0);
    const int b_chunk  = (lane >> 3) & 1;

    for (int i = 0; i < nch; i++) {
        CP_WAIT1();
        __syncthreads();
        if (i + 2 < nch) issue_stage((i + 2) % 3, i + 2);
        else CP_COMMIT();

        uint32_t sbase = smem + (i % 3) * STAGE;
        uint32_t As = sbase, Bs = sbase + ATILE;

        #pragma unroll
        for (int ks = 0; ks < 4; ks++) {
            uint32_t a[2][4];
            #pragma unroll
            for (int mt = 0; mt < 2; mt++) {
                int row = wm * 32 + mt * 16 + a_row_in;
                int ch  = ks * 2 + a_chunk;
                ldsm_x4(As + swz128((uint32_t)(row * 128 + ch * 16)),
                        a[mt][0], a[mt][1], a[mt][2], a[mt][3]);
            }
            uint32_t b[NT][2];
            #pragma unroll
            for (int np = 0; np < NT/2; np++) {
                int row = wn * WN + np * 16 + b_row_in;
                int ch  = ks * 2 + b_chunk;
                ldsm_x4(Bs + swz128((uint32_t)(row * 128 + ch * 16)),
                        b[np*2][0], b[np*2][1], b[np*2+1][0], b[np*2+1][1]);
            }
            #pragma unroll
            for (int mt = 0; mt < 2; mt++)
                #pragma unroll
                for (int nt = 0; nt < NT; nt++)
                    mma16816(acc[mt][nt], a[mt], b[nt]);
        }
        __syncthreads();
    }
    CP_WAIT0();

    #pragma unroll
    for (int mt = 0; mt < 2; mt++) {
        int r0g = m0 + wm * 32 + mt * 16 + (lane >> 2);
        #pragma unroll
        for (int nt = 0; nt < NT; nt++) {
            int col = n0 + wn * WN + nt * 8 + (lane & 3) * 2;
            if (col >= Nreal) continue;
            float bx = 0.f, by = 0.f;
            if (bias) { bx = bias[col]; by = bias[col + 1]; }
            float2 v0 = make_float2(acc[mt][nt][0] + bx, acc[mt][nt][1] + by);
            float2 v1 = make_float2(acc[mt][nt][2] + bx, acc[mt][nt][3] + by);
            *(float2*)(C + (long long)r0g * Nreal + col) = v0;
            *(float2*)(C + (long long)(r0g + 8) * Nreal + col) = v1;
        }
    }
}

// ---------------------------------------------------------------------------
// LSTM elementwise; also writes fp16 h for the logits GEMM A side
// ---------------------------------------------------------------------------
__global__ void lstm_kernel(const float* __restrict__ b_ih,
                            const float* __restrict__ b_hh,
                            float* __restrict__ h_out,
                            float* __restrict__ c_out) {
    int idx = blockIdx.x * blockDim.x + threadIdx.x;
    if (idx >= B_*E_) return;
    int b = idx >> 10, e = idx & (E_ - 1);
    const float* g = g_gates + (long long)b * G4E_;
    float xi = g[e]        + b_ih[e]        + b_hh[e];
    float xf = g[E_   + e] + b_ih[E_   + e] + b_hh[E_   + e];
    float xg = g[2*E_ + e] + b_ih[2*E_ + e] + b_hh[2*E_ + e];
    float xo = g[3*E_ + e] + b_ih[3*E_ + e] + b_hh[3*E_ + e];
    float ig = 1.f / (1.f + __expf(-xi));
    float fg = 1.f / (1.f + __expf(-xf));
    float gg = tanhf(xg);
    float og = 1.f / (1.f + __expf(-xo));
    float c  = fg * g_ctx[idx] + ig * gg;
    float h  = og * tanhf(c);
    h_out[idx] = h;
    c_out[idx] = c;
    g_h[idx] = __float2half_rn(h);
}

// ---------------------------------------------------------------------------
// Lazily-created side stream + events (created OUTSIDE capture, on the
// correctness call; reused by the capture call). No device memory involved.
// ---------------------------------------------------------------------------
static cudaStream_t s_side = nullptr;
static cudaEvent_t  s_evFork = nullptr, s_evG = nullptr, s_evP = nullptr;

extern "C" void kernel_launch(void* const* d_in, const int* in_sizes, int n_in,
                              void* d_out, int out_size) {
    const void *p_tgt=0, *p_enc=0, *p_h0=0, *p_pad=0, *p_emb=0, *p_wproj=0,
               *p_wih=0, *p_whh=0, *p_bih=0, *p_bhh=0, *p_bproj=0;
    int seen_be = 0, seen_ve = 0, seen_w = 0, seen_b4 = 0;
    for (int i = 0; i < n_in; i++) {
        long long s = in_sizes[i];
        if      (s == 512)                  p_tgt = d_in[i];
        else if (s == (long long)B_*ML_*E_) p_enc = d_in[i];
        else if (s == (long long)B_*E_)     { if (seen_be++ == 0) p_h0 = d_in[i]; }
        else if (s == B_*ML_)               p_pad = d_in[i];
        else if (s == (long long)V_*E_)     { if (seen_ve++ == 0) p_emb = d_in[i]; else p_wproj = d_in[i]; }
        else if (s == (long long)G4E_*E_)   { if (seen_w++  == 0) p_wih = d_in[i]; else p_whh = d_in[i]; }
        else if (s == G4E_)                 { if (seen_b4++ == 0) p_bih = d_in[i]; else p_bhh = d_in[i]; }
        else if (s == V_)                   p_bproj = d_in[i];
    }

    const int*   tgt    = (const int*)p_tgt;
    const float* enc    = (const float*)p_enc;
    const float* h0     = (const float*)p_h0;
    const float* emb    = (const float*)p_emb;
    const float* w_ih   = (const float*)p_wih;
    const float* w_hh   = (const float*)p_whh;
    const float* b_ih   = (const float*)p_bih;
    const float* b_hh   = (const float*)p_bhh;
    const float* w_proj = (const float*)p_wproj;
    const float* b_proj = (const float*)p_bproj;

    float* out    = (float*)d_out;
    float* logits = out;
    float* h_out  = out + (long long)B_ * V_;
    float* c_out  = h_out + (long long)B_ * E_;

    float *gates;
    cudaGetSymbolAddress((void**)&gates, g_gates);
    __half *wp, *wg, *ag, *hh;
    cudaGetSymbolAddress((void**)&wp, g_wp);
    cudaGetSymbolAddress((void**)&wg, g_wg);
    cudaGetSymbolAddress((void**)&ag, g_ag);
    cudaGetSymbolAddress((void**)&hh, g_h);

    const int SMEM128 = 3 * (128*128 + 16384);   // 96 KB
    const int SMEM64  = 3 * (64*128 + 16384);    // 72 KB
    cudaFuncSetAttribute(gemm_fp16_mma<128>, cudaFuncAttributeMaxDynamicSharedMemorySize, SMEM128);
    cudaFuncSetAttribute(gemm_fp16_mma<64>,  cudaFuncAttributeMaxDynamicSharedMemorySize, SMEM64);

    if (s_side == nullptr) {
        cudaStreamCreateWithFlags(&s_side, cudaStreamNonBlocking);
        cudaEventCreateWithFlags(&s_evFork, cudaEventDisableTiming);
        cudaEventCreateWithFlags(&s_evG,    cudaEventDisableTiming);
        cudaEventCreateWithFlags(&s_evP,    cudaEventDisableTiming);
    }

    // ---- fork: weight conversion on the side stream ----
    cudaEventRecord(s_evFork, 0);
    cudaStreamWaitEvent(s_side, s_evFork, 0);
    {
        long long tg = (long long)G4E_ * (KGATE/8);
        conv_wgate_kernel<<<(unsigned)((tg + 255)/256), 256, 0, s_side>>>(w_ih, w_hh);
        cudaEventRecord(s_evG, s_side);
        long long tot = (long long)NPADV * (E_/8);
        conv_wproj_kernel<<<(unsigned)((tot + 255)/256), 256, 0, s_side>>>(w_proj);
        cudaEventRecord(s_evP, s_side);
    }

    // ---- main stream ----
    detect_pad_kernel<<<1, 1024>>>((const unsigned char*)p_pad);
    gather_words_kernel<<<(B_*(E_/4) + 255)/256, 256>>>(tgt, emb);
    attn_kernel<<<B_, 256>>>(enc, h0, p_pad);

    // join: gates GEMM needs converted [w_ih|w_hh]
    cudaStreamWaitEvent(0, s_evG, 0);
    {
        dim3 grid(B_/64, G4E_/128);
        gemm_fp16_mma<64><<<grid, 256, SMEM64>>>(ag, wg, gates, nullptr, KGATE, G4E_);
    }

    lstm_kernel<<<(B_*E_ + 255)/256, 256>>>(b_ih, b_hh, h_out, c_out);

    // join: logits GEMM needs converted w_proj
    cudaStreamWaitEvent(0, s_evP, 0);
    {
        dim3 grid(B_/128, NPADV/128);
        gemm_fp16_mma<128><<<grid, 256, SMEM128>>>(hh, wp, logits, b_proj, E_, V_);
    }
}